// round 2
// baseline (speedup 1.0000x reference)
#include <cuda_runtime.h>
#include <cuda_fp16.h>
#include <cuda_bf16.h>

// Problem constants
#define DD   64      // input dim
#define HH   256     // hidden dim
#define BB   256     // batch
#define TT   512     // encoder timesteps
#define GG   1024    // 4*H
#define WOUT 96      // decoder steps

// ---------------- static scratch (no cudaMalloc allowed) ----------------
__device__ float  g_W0[GG * 320];          // [p][0:64]=Wih0, [64:320]=Whh0 (rows gate-permuted)
__device__ float  g_b0[GG];
__device__ float  g_W1[GG * 512];          // [p][0:256]=Wih1, [256:512]=Whh1
__device__ float  g_b1[GG];
__device__ float  g_Wd[GG * 768];          // [p][0:512]=Wih_d, [512:768]=Whh_d
__device__ float  g_bd[GG];
__device__ float  g_enc1[(size_t)BB * TT * HH];   // layer-0 outputs, fp32 (134MB)
__device__ __half g_enc [(size_t)BB * TT * HH];   // layer-1 outputs, fp16 (67MB, fits L2)
__device__ float  g_h0[2][BB * HH];
__device__ float  g_c0[BB * HH];
__device__ float  g_h1[2][BB * HH];
__device__ float  g_c1[BB * HH];
__device__ float  g_inp[BB * 512];         // decoder [p | ctx]

// ---------------- prep: gate-interleave weights, zero state ----------------
// permuted row p = 4k+q  <-  original row q*H + k   (i,f,g,o interleaved per h-index)
__global__ void prep_kernel(
    const float* __restrict__ Wih0, const float* __restrict__ Whh0,
    const float* __restrict__ bih0, const float* __restrict__ bhh0,
    const float* __restrict__ Wih1, const float* __restrict__ Whh1,
    const float* __restrict__ bih1, const float* __restrict__ bhh1,
    const float* __restrict__ Wihd, const float* __restrict__ Whhd,
    const float* __restrict__ bihd, const float* __restrict__ bhhd)
{
    int p = blockIdx.x;          // 0..1023
    int k = p >> 2, q = p & 3;
    int r = q * HH + k;
    int tid = threadIdx.x;       // 256 threads

    if (tid < 64) g_W0[p * 320 + tid] = Wih0[r * 64 + tid];
    g_W0[p * 320 +  64 + tid] = Whh0[r * 256 + tid];

    g_W1[p * 512 +       tid] = Wih1[r * 256 + tid];
    g_W1[p * 512 + 256 + tid] = Whh1[r * 256 + tid];

    g_Wd[p * 768 +       tid] = Wihd[r * 512 + tid];
    g_Wd[p * 768 + 256 + tid] = Wihd[r * 512 + 256 + tid];
    g_Wd[p * 768 + 512 + tid] = Whhd[r * 256 + tid];

    if (tid == 0) {
        g_b0[p] = bih0[r] + bhh0[r];
        g_b1[p] = bih1[r] + bhh1[r];
        g_bd[p] = bihd[r] + bhhd[r];
    }
    int idx = p * 256 + tid;     // covers 262144 >= 65536
    if (idx < BB * HH) {
        g_h0[0][idx] = 0.f; g_h0[1][idx] = 0.f; g_c0[idx] = 0.f;
        g_h1[0][idx] = 0.f; g_h1[1][idx] = 0.f; g_c1[idx] = 0.f;
    }
}

// ---------------- fused GEMM + LSTM-cell step (tile 32x64, 256 thr) ----------------
// gates(BMxBN) = [A0|A1] @ W^T + bias ; epilogue does the LSTM cell update.
// Columns are gate-interleaved: cols 4k..4k+3 = (i,f,g,o) of h-index col0/4 + tx.
__device__ __forceinline__ float sigf(float x) { return 1.f / (1.f + expf(-x)); }

__device__ __forceinline__ void lstm_gemm_tile(
    const float* __restrict__ A0, long long lda0, int K0,
    const float* __restrict__ A1, long long lda1, int K1,
    const float* __restrict__ W,  int ldw,
    const float* __restrict__ bias,
    float* __restrict__ c, float* __restrict__ h_out,
    float* __restrict__ seq_out, __half* __restrict__ seqh_out, long long seq_stride,
    int bx, int by)
{
    __shared__ float As[16][34];   // [kk][row], float2-aligned rows
    __shared__ float Ws[16][68];   // [kk][col], float4-aligned rows
    const int tid = threadIdx.x;
    const int tx = tid & 15, ty = tid >> 4;
    const int row0 = by * 32, col0 = bx * 64;
    float acc[2][4] = {{0.f,0.f,0.f,0.f},{0.f,0.f,0.f,0.f}};
    const int Ktot = K0 + K1;

    for (int kt = 0; kt < Ktot; kt += 16) {
        const float* Aseg; long long ldA; int kl;
        if (kt < K0) { Aseg = A0; ldA = lda0; kl = kt; }
        else         { Aseg = A1; ldA = lda1; kl = kt - K0; }
        // A tile: 32x16 = 512 elems, 2 per thread (coalesced 16-float row chunks)
        {
            int r = tid >> 4, kk = tid & 15;
            As[kk][r] = Aseg[(long long)(row0 + r) * ldA + kl + kk];
            int i1 = tid + 256; r = i1 >> 4; kk = i1 & 15;
            As[kk][r] = Aseg[(long long)(row0 + r) * ldA + kl + kk];
        }
        // W tile: 64x16 = 1024 elems, 4 per thread
        #pragma unroll
        for (int i = 0; i < 4; i++) {
            int idx = tid + i * 256;
            int cc = idx >> 4, kk = idx & 15;
            Ws[kk][cc] = W[(long long)(col0 + cc) * ldw + kt + kk];
        }
        __syncthreads();
        #pragma unroll
        for (int kk = 0; kk < 16; kk++) {
            float2 av = *reinterpret_cast<const float2*>(&As[kk][ty * 2]);
            float4 wv = *reinterpret_cast<const float4*>(&Ws[kk][tx * 4]);
            acc[0][0] = fmaf(av.x, wv.x, acc[0][0]);
            acc[0][1] = fmaf(av.x, wv.y, acc[0][1]);
            acc[0][2] = fmaf(av.x, wv.z, acc[0][2]);
            acc[0][3] = fmaf(av.x, wv.w, acc[0][3]);
            acc[1][0] = fmaf(av.y, wv.x, acc[1][0]);
            acc[1][1] = fmaf(av.y, wv.y, acc[1][1]);
            acc[1][2] = fmaf(av.y, wv.z, acc[1][2]);
            acc[1][3] = fmaf(av.y, wv.w, acc[1][3]);
        }
        __syncthreads();
    }

    const int hidx = (col0 >> 2) + tx;
    float4 bv = *reinterpret_cast<const float4*>(&bias[col0 + tx * 4]);
    #pragma unroll
    for (int rr = 0; rr < 2; rr++) {
        int row = row0 + ty * 2 + rr;
        float iv = sigf(acc[rr][0] + bv.x);
        float fv = sigf(acc[rr][1] + bv.y);
        float gv = tanhf(acc[rr][2] + bv.z);
        float ov = sigf(acc[rr][3] + bv.w);
        int ci = row * HH + hidx;
        float cn = fv * c[ci] + iv * gv;
        c[ci] = cn;
        float hv = ov * tanhf(cn);
        h_out[ci] = hv;
        if (seq_out)  seq_out [(long long)row * seq_stride + hidx] = hv;
        if (seqh_out) seqh_out[(long long)row * seq_stride + hidx] = __float2half(hv);
    }
}

// ---------------- encoder: pipelined layer0(step t) + layer1(step t-1) ----------------
__global__ __launch_bounds__(256)
void enc_step_kernel(const float* __restrict__ x_in, int t)
{
    if (blockIdx.z == 0) {
        if (t >= TT) return;
        lstm_gemm_tile(x_in + (long long)t * DD, (long long)TT * DD, DD,
                       g_h0[t & 1], HH, HH,
                       g_W0, 320, g_b0,
                       g_c0, g_h0[(t + 1) & 1],
                       g_enc1 + (long long)t * HH, nullptr, (long long)TT * HH,
                       blockIdx.x, blockIdx.y);
    } else {
        if (t == 0) return;
        int tt = t - 1;
        lstm_gemm_tile(g_enc1 + (long long)tt * HH, (long long)TT * HH, HH,
                       g_h1[tt & 1], HH, HH,
                       g_W1, 512, g_b1,
                       g_c1, g_h1[(tt + 1) & 1],
                       nullptr, g_enc + (long long)tt * HH, (long long)TT * HH,
                       blockIdx.x, blockIdx.y);
    }
}

// ---------------- decoder attention (single pass, online softmax) + p-projection ----
__global__ __launch_bounds__(256)
void dec_attn_kernel(const float* __restrict__ prev_y, long long ldy,
                     const float* __restrict__ Wp, const float* __restrict__ bp, int s)
{
    int b = blockIdx.x;
    const float* h = g_h1[s & 1] + b * HH;
    __shared__ float sh_h[HH];
    __shared__ float sh_py[DD];
    __shared__ float sh_m[8], sh_s[8];
    __shared__ float sh_part[8][HH];
    int tid = threadIdx.x, lane = tid & 31, w = tid >> 5;

    sh_h[tid] = h[tid];
    if (tid < DD) sh_py[tid] = prev_y[(long long)b * ldy + tid];
    __syncthreads();

    float m = -1e30f, ssum = 0.f;
    float accv[8];
    #pragma unroll
    for (int c2 = 0; c2 < 8; c2++) accv[c2] = 0.f;
    const __half* ebase = g_enc + (long long)b * TT * HH;

    for (int i = 0; i < 64; i++) {
        int t = w * 64 + i;
        const __half* e = ebase + (long long)t * HH;
        float v[8];
        float dot = 0.f;
        #pragma unroll
        for (int c2 = 0; c2 < 8; c2++) {
            v[c2] = __half2float(e[lane + 32 * c2]);
            dot = fmaf(v[c2], sh_h[lane + 32 * c2], dot);
        }
        #pragma unroll
        for (int o = 16; o > 0; o >>= 1) dot += __shfl_xor_sync(0xffffffffu, dot, o);
        float score = dot * 0.0625f;                 // / sqrt(256)
        float nm  = fmaxf(m, score);
        float esc = __expf(m - nm);
        float p   = __expf(score - nm);
        ssum = ssum * esc + p;
        #pragma unroll
        for (int c2 = 0; c2 < 8; c2++) accv[c2] = accv[c2] * esc + p * v[c2];
        m = nm;
    }
    if (lane == 0) { sh_m[w] = m; sh_s[w] = ssum; }
    #pragma unroll
    for (int c2 = 0; c2 < 8; c2++) sh_part[w][lane + 32 * c2] = accv[c2];
    __syncthreads();

    float M = sh_m[0];
    #pragma unroll
    for (int ww = 1; ww < 8; ww++) M = fmaxf(M, sh_m[ww]);
    float num = 0.f, den = 0.f;
    #pragma unroll
    for (int ww = 0; ww < 8; ww++) {
        float f = __expf(sh_m[ww] - M);
        den += f * sh_s[ww];
        num += f * sh_part[ww][tid];
    }
    g_inp[b * 512 + 256 + tid] = num / den;          // ctx

    float pv = bp[tid];
    #pragma unroll 8
    for (int d = 0; d < DD; d++) pv = fmaf(sh_py[d], Wp[tid * DD + d], pv);
    g_inp[b * 512 + tid] = pv;                       // prev_y @ Wp^T + bp
}

// ---------------- decoder LSTM cell ----------------
__global__ __launch_bounds__(256)
void dec_lstm_kernel(int s)
{
    lstm_gemm_tile(g_inp, 512, 512,
                   g_h1[s & 1], HH, HH,
                   g_Wd, 768, g_bd,
                   g_c1, g_h1[(s + 1) & 1],
                   nullptr, nullptr, 0,
                   blockIdx.x, blockIdx.y);
}

// ---------------- decoder output: y = [h_new | ctx] @ Wo^T + bo ----------------
__global__ __launch_bounds__(256)
void dec_y_kernel(float* __restrict__ out, const float* __restrict__ Wo,
                  const float* __restrict__ bo, int s)
{
    __shared__ float sA[16][512];
    int tid = threadIdx.x;
    int rb = blockIdx.x * 16;
    const float* hN = g_h1[(s + 1) & 1];
    for (int i = tid; i < 16 * 512; i += 256) {
        int r = i >> 9, k = i & 511;
        sA[r][k] = (k < 256) ? hN[(rb + r) * HH + k] : g_inp[(rb + r) * 512 + k];
    }
    __syncthreads();
    int j  = tid & 63;
    int r0 = (tid >> 6) * 4;
    float a0 = bo[j], a1 = a0, a2 = a0, a3 = a0;
    const float4* Wrow = reinterpret_cast<const float4*>(Wo + j * 512);
    for (int k4 = 0; k4 < 128; k4++) {
        float4 wv = Wrow[k4];
        int k = k4 * 4;
        a0 = fmaf(wv.x, sA[r0+0][k], a0); a0 = fmaf(wv.y, sA[r0+0][k+1], a0);
        a0 = fmaf(wv.z, sA[r0+0][k+2], a0); a0 = fmaf(wv.w, sA[r0+0][k+3], a0);
        a1 = fmaf(wv.x, sA[r0+1][k], a1); a1 = fmaf(wv.y, sA[r0+1][k+1], a1);
        a1 = fmaf(wv.z, sA[r0+1][k+2], a1); a1 = fmaf(wv.w, sA[r0+1][k+3], a1);
        a2 = fmaf(wv.x, sA[r0+2][k], a2); a2 = fmaf(wv.y, sA[r0+2][k+1], a2);
        a2 = fmaf(wv.z, sA[r0+2][k+2], a2); a2 = fmaf(wv.w, sA[r0+2][k+3], a2);
        a3 = fmaf(wv.x, sA[r0+3][k], a3); a3 = fmaf(wv.y, sA[r0+3][k+1], a3);
        a3 = fmaf(wv.z, sA[r0+3][k+2], a3); a3 = fmaf(wv.w, sA[r0+3][k+3], a3);
    }
    long long base = ((long long)(rb + r0) * WOUT + s) * DD + j;
    out[base]                        = a0;
    out[base + 1LL * WOUT * DD]      = a1;
    out[base + 2LL * WOUT * DD]      = a2;
    out[base + 3LL * WOUT * DD]      = a3;
}

// ---------------- launch ----------------
extern "C" void kernel_launch(void* const* d_in, const int* in_sizes, int n_in,
                              void* d_out, int out_size)
{
    const float* x_in = (const float*)d_in[0];
    // w_out (scalar) may or may not be materialized as an input; detect via size.
    int o = (n_in > 1 && in_sizes[1] == 1) ? 2 : 1;
    const float* Wih0 = (const float*)d_in[o + 0];
    const float* Whh0 = (const float*)d_in[o + 1];
    const float* bih0 = (const float*)d_in[o + 2];
    const float* bhh0 = (const float*)d_in[o + 3];
    const float* Wih1 = (const float*)d_in[o + 4];
    const float* Whh1 = (const float*)d_in[o + 5];
    const float* bih1 = (const float*)d_in[o + 6];
    const float* bhh1 = (const float*)d_in[o + 7];
    const float* Wihd = (const float*)d_in[o + 8];
    const float* Whhd = (const float*)d_in[o + 9];
    const float* bihd = (const float*)d_in[o + 10];
    const float* bhhd = (const float*)d_in[o + 11];
    const float* Wp   = (const float*)d_in[o + 12];
    const float* bp   = (const float*)d_in[o + 13];
    const float* Wo   = (const float*)d_in[o + 14];
    const float* bo   = (const float*)d_in[o + 15];
    float* out = (float*)d_out;

    prep_kernel<<<GG, 256>>>(Wih0, Whh0, bih0, bhh0,
                             Wih1, Whh1, bih1, bhh1,
                             Wihd, Whhd, bihd, bhhd);

    // encoder: pipelined two-layer scan, 513 launches
    for (int t = 0; t <= TT; t++)
        enc_step_kernel<<<dim3(16, 8, 2), 256>>>(x_in, t);

    // decoder: 96 steps
    for (int s = 0; s < WOUT; s++) {
        const float* py = (s == 0) ? (x_in + (long long)(TT - 1) * DD)
                                   : (out + (long long)(s - 1) * DD);
        long long ldy = (s == 0) ? (long long)TT * DD : (long long)WOUT * DD;
        dec_attn_kernel<<<BB, 256>>>(py, ldy, Wp, bp, s);
        dec_lstm_kernel<<<dim3(16, 8), 256>>>(s);
        dec_y_kernel<<<16, 256>>>(out, Wo, bo, s);
    }
}

// round 3
// speedup vs baseline: 1.0021x; 1.0021x over previous
#include <cuda_runtime.h>
#include <cuda_fp16.h>
#include <cuda_bf16.h>

// Problem constants
#define DD   64      // input dim
#define HH   256     // hidden dim
#define BB   256     // batch
#define TT   512     // encoder timesteps
#define GG   1024    // 4*H
#define WOUT 96      // decoder steps

// ---------------- static scratch (no cudaMalloc allowed) ----------------
__device__ float  g_W0[GG * 320];          // [p][0:64]=Wih0, [64:320]=Whh0 (rows gate-permuted)
__device__ float  g_b0[GG];
__device__ float  g_W1[GG * 512];          // [p][0:256]=Wih1, [256:512]=Whh1
__device__ float  g_b1[GG];
__device__ float  g_Wd[GG * 768];          // [p][0:512]=Wih_d, [512:768]=Whh_d
__device__ float  g_bd[GG];
__device__ float  g_enc1[(size_t)BB * TT * HH];   // layer-0 outputs, fp32 (134MB)
__device__ __half g_enc [(size_t)BB * TT * HH];   // layer-1 outputs, fp16 (67MB, fits L2)
__device__ float  g_h0[2][BB * HH];
__device__ float  g_c0[BB * HH];
__device__ float  g_h1[2][BB * HH];
__device__ float  g_c1[BB * HH];
__device__ float  g_inp[BB * 512];         // decoder [p | ctx]

// ---------------- prep: gate-interleave weights, zero state ----------------
// permuted row p = 4k+q  <-  original row q*H + k   (i,f,g,o interleaved per h-index)
__global__ void prep_kernel(
    const float* __restrict__ Wih0, const float* __restrict__ Whh0,
    const float* __restrict__ bih0, const float* __restrict__ bhh0,
    const float* __restrict__ Wih1, const float* __restrict__ Whh1,
    const float* __restrict__ bih1, const float* __restrict__ bhh1,
    const float* __restrict__ Wihd, const float* __restrict__ Whhd,
    const float* __restrict__ bihd, const float* __restrict__ bhhd)
{
    int p = blockIdx.x;          // 0..1023
    int k = p >> 2, q = p & 3;
    int r = q * HH + k;
    int tid = threadIdx.x;       // 256 threads

    if (tid < 64) g_W0[p * 320 + tid] = Wih0[r * 64 + tid];
    g_W0[p * 320 +  64 + tid] = Whh0[r * 256 + tid];

    g_W1[p * 512 +       tid] = Wih1[r * 256 + tid];
    g_W1[p * 512 + 256 + tid] = Whh1[r * 256 + tid];

    g_Wd[p * 768 +       tid] = Wihd[r * 512 + tid];
    g_Wd[p * 768 + 256 + tid] = Wihd[r * 512 + 256 + tid];
    g_Wd[p * 768 + 512 + tid] = Whhd[r * 256 + tid];

    if (tid == 0) {
        g_b0[p] = bih0[r] + bhh0[r];
        g_b1[p] = bih1[r] + bhh1[r];
        g_bd[p] = bihd[r] + bhhd[r];
    }
    int idx = p * 256 + tid;     // covers 262144 >= 65536
    if (idx < BB * HH) {
        g_h0[0][idx] = 0.f; g_h0[1][idx] = 0.f; g_c0[idx] = 0.f;
        g_h1[0][idx] = 0.f; g_h1[1][idx] = 0.f; g_c1[idx] = 0.f;
    }
}

// ---------------- fused GEMM + LSTM-cell step (tile 32x64, 256 thr) ----------------
// gates(BMxBN) = [A0|A1] @ W^T + bias ; epilogue does the LSTM cell update.
// Columns are gate-interleaved: cols 4k..4k+3 = (i,f,g,o) of h-index col0/4 + tx.
__device__ __forceinline__ float sigf(float x) { return 1.f / (1.f + expf(-x)); }

__device__ __forceinline__ void lstm_gemm_tile(
    const float* __restrict__ A0, long long lda0, int K0,
    const float* __restrict__ A1, long long lda1, int K1,
    const float* __restrict__ W,  int ldw,
    const float* __restrict__ bias,
    float* __restrict__ c, float* __restrict__ h_out,
    float* __restrict__ seq_out, __half* __restrict__ seqh_out, long long seq_stride,
    int bx, int by)
{
    __shared__ float As[16][34];   // [kk][row], float2-aligned rows
    __shared__ float Ws[16][68];   // [kk][col], float4-aligned rows
    const int tid = threadIdx.x;
    const int tx = tid & 15, ty = tid >> 4;
    const int row0 = by * 32, col0 = bx * 64;
    float acc[2][4] = {{0.f,0.f,0.f,0.f},{0.f,0.f,0.f,0.f}};
    const int Ktot = K0 + K1;

    for (int kt = 0; kt < Ktot; kt += 16) {
        const float* Aseg; long long ldA; int kl;
        if (kt < K0) { Aseg = A0; ldA = lda0; kl = kt; }
        else         { Aseg = A1; ldA = lda1; kl = kt - K0; }
        // A tile: 32x16 = 512 elems, 2 per thread (coalesced 16-float row chunks)
        {
            int r = tid >> 4, kk = tid & 15;
            As[kk][r] = Aseg[(long long)(row0 + r) * ldA + kl + kk];
            int i1 = tid + 256; r = i1 >> 4; kk = i1 & 15;
            As[kk][r] = Aseg[(long long)(row0 + r) * ldA + kl + kk];
        }
        // W tile: 64x16 = 1024 elems, 4 per thread
        #pragma unroll
        for (int i = 0; i < 4; i++) {
            int idx = tid + i * 256;
            int cc = idx >> 4, kk = idx & 15;
            Ws[kk][cc] = W[(long long)(col0 + cc) * ldw + kt + kk];
        }
        __syncthreads();
        #pragma unroll
        for (int kk = 0; kk < 16; kk++) {
            float2 av = *reinterpret_cast<const float2*>(&As[kk][ty * 2]);
            float4 wv = *reinterpret_cast<const float4*>(&Ws[kk][tx * 4]);
            acc[0][0] = fmaf(av.x, wv.x, acc[0][0]);
            acc[0][1] = fmaf(av.x, wv.y, acc[0][1]);
            acc[0][2] = fmaf(av.x, wv.z, acc[0][2]);
            acc[0][3] = fmaf(av.x, wv.w, acc[0][3]);
            acc[1][0] = fmaf(av.y, wv.x, acc[1][0]);
            acc[1][1] = fmaf(av.y, wv.y, acc[1][1]);
            acc[1][2] = fmaf(av.y, wv.z, acc[1][2]);
            acc[1][3] = fmaf(av.y, wv.w, acc[1][3]);
        }
        __syncthreads();
    }

    const int hidx = (col0 >> 2) + tx;
    float4 bv = *reinterpret_cast<const float4*>(&bias[col0 + tx * 4]);
    #pragma unroll
    for (int rr = 0; rr < 2; rr++) {
        int row = row0 + ty * 2 + rr;
        float iv = sigf(acc[rr][0] + bv.x);
        float fv = sigf(acc[rr][1] + bv.y);
        float gv = tanhf(acc[rr][2] + bv.z);
        float ov = sigf(acc[rr][3] + bv.w);
        int ci = row * HH + hidx;
        float cn = fv * c[ci] + iv * gv;
        c[ci] = cn;
        float hv = ov * tanhf(cn);
        h_out[ci] = hv;
        if (seq_out)  seq_out [(long long)row * seq_stride + hidx] = hv;
        if (seqh_out) seqh_out[(long long)row * seq_stride + hidx] = __float2half(hv);
    }
}

// ---------------- encoder: pipelined layer0(step t) + layer1(step t-1) ----------------
__global__ __launch_bounds__(256)
void enc_step_kernel(const float* __restrict__ x_in, int t)
{
    if (blockIdx.z == 0) {
        if (t >= TT) return;
        lstm_gemm_tile(x_in + (long long)t * DD, (long long)TT * DD, DD,
                       g_h0[t & 1], HH, HH,
                       g_W0, 320, g_b0,
                       g_c0, g_h0[(t + 1) & 1],
                       g_enc1 + (long long)t * HH, nullptr, (long long)TT * HH,
                       blockIdx.x, blockIdx.y);
    } else {
        if (t == 0) return;
        int tt = t - 1;
        lstm_gemm_tile(g_enc1 + (long long)tt * HH, (long long)TT * HH, HH,
                       g_h1[tt & 1], HH, HH,
                       g_W1, 512, g_b1,
                       g_c1, g_h1[(tt + 1) & 1],
                       nullptr, g_enc + (long long)tt * HH, (long long)TT * HH,
                       blockIdx.x, blockIdx.y);
    }
}

// ---------------- decoder attention (single pass, online softmax) + p-projection ----
__global__ __launch_bounds__(256)
void dec_attn_kernel(const float* __restrict__ prev_y, long long ldy,
                     const float* __restrict__ Wp, const float* __restrict__ bp, int s)
{
    int b = blockIdx.x;
    const float* h = g_h1[s & 1] + b * HH;
    __shared__ float sh_h[HH];
    __shared__ float sh_py[DD];
    __shared__ float sh_m[8], sh_s[8];
    __shared__ float sh_part[8][HH];
    int tid = threadIdx.x, lane = tid & 31, w = tid >> 5;

    sh_h[tid] = h[tid];
    if (tid < DD) sh_py[tid] = prev_y[(long long)b * ldy + tid];
    __syncthreads();

    float m = -1e30f, ssum = 0.f;
    float accv[8];
    #pragma unroll
    for (int c2 = 0; c2 < 8; c2++) accv[c2] = 0.f;
    const __half* ebase = g_enc + (long long)b * TT * HH;

    for (int i = 0; i < 64; i++) {
        int t = w * 64 + i;
        const __half* e = ebase + (long long)t * HH;
        float v[8];
        float dot = 0.f;
        #pragma unroll
        for (int c2 = 0; c2 < 8; c2++) {
            v[c2] = __half2float(e[lane + 32 * c2]);
            dot = fmaf(v[c2], sh_h[lane + 32 * c2], dot);
        }
        #pragma unroll
        for (int o = 16; o > 0; o >>= 1) dot += __shfl_xor_sync(0xffffffffu, dot, o);
        float score = dot * 0.0625f;                 // / sqrt(256)
        float nm  = fmaxf(m, score);
        float esc = __expf(m - nm);
        float p   = __expf(score - nm);
        ssum = ssum * esc + p;
        #pragma unroll
        for (int c2 = 0; c2 < 8; c2++) accv[c2] = accv[c2] * esc + p * v[c2];
        m = nm;
    }
    if (lane == 0) { sh_m[w] = m; sh_s[w] = ssum; }
    #pragma unroll
    for (int c2 = 0; c2 < 8; c2++) sh_part[w][lane + 32 * c2] = accv[c2];
    __syncthreads();

    float M = sh_m[0];
    #pragma unroll
    for (int ww = 1; ww < 8; ww++) M = fmaxf(M, sh_m[ww]);
    float num = 0.f, den = 0.f;
    #pragma unroll
    for (int ww = 0; ww < 8; ww++) {
        float f = __expf(sh_m[ww] - M);
        den += f * sh_s[ww];
        num += f * sh_part[ww][tid];
    }
    g_inp[b * 512 + 256 + tid] = num / den;          // ctx

    float pv = bp[tid];
    #pragma unroll 8
    for (int d = 0; d < DD; d++) pv = fmaf(sh_py[d], Wp[tid * DD + d], pv);
    g_inp[b * 512 + tid] = pv;                       // prev_y @ Wp^T + bp
}

// ---------------- decoder LSTM cell ----------------
__global__ __launch_bounds__(256)
void dec_lstm_kernel(int s)
{
    lstm_gemm_tile(g_inp, 512, 512,
                   g_h1[s & 1], HH, HH,
                   g_Wd, 768, g_bd,
                   g_c1, g_h1[(s + 1) & 1],
                   nullptr, nullptr, 0,
                   blockIdx.x, blockIdx.y);
}

// ---------------- decoder output: y = [h_new | ctx] @ Wo^T + bo ----------------
__global__ __launch_bounds__(256)
void dec_y_kernel(float* __restrict__ out, const float* __restrict__ Wo,
                  const float* __restrict__ bo, int s)
{
    __shared__ float sA[16][512];
    int tid = threadIdx.x;
    int rb = blockIdx.x * 16;
    const float* hN = g_h1[(s + 1) & 1];
    for (int i = tid; i < 16 * 512; i += 256) {
        int r = i >> 9, k = i & 511;
        sA[r][k] = (k < 256) ? hN[(rb + r) * HH + k] : g_inp[(rb + r) * 512 + k];
    }
    __syncthreads();
    int j  = tid & 63;
    int r0 = (tid >> 6) * 4;
    float a0 = bo[j], a1 = a0, a2 = a0, a3 = a0;
    const float4* Wrow = reinterpret_cast<const float4*>(Wo + j * 512);
    for (int k4 = 0; k4 < 128; k4++) {
        float4 wv = Wrow[k4];
        int k = k4 * 4;
        a0 = fmaf(wv.x, sA[r0+0][k], a0); a0 = fmaf(wv.y, sA[r0+0][k+1], a0);
        a0 = fmaf(wv.z, sA[r0+0][k+2], a0); a0 = fmaf(wv.w, sA[r0+0][k+3], a0);
        a1 = fmaf(wv.x, sA[r0+1][k], a1); a1 = fmaf(wv.y, sA[r0+1][k+1], a1);
        a1 = fmaf(wv.z, sA[r0+1][k+2], a1); a1 = fmaf(wv.w, sA[r0+1][k+3], a1);
        a2 = fmaf(wv.x, sA[r0+2][k], a2); a2 = fmaf(wv.y, sA[r0+2][k+1], a2);
        a2 = fmaf(wv.z, sA[r0+2][k+2], a2); a2 = fmaf(wv.w, sA[r0+2][k+3], a2);
        a3 = fmaf(wv.x, sA[r0+3][k], a3); a3 = fmaf(wv.y, sA[r0+3][k+1], a3);
        a3 = fmaf(wv.z, sA[r0+3][k+2], a3); a3 = fmaf(wv.w, sA[r0+3][k+3], a3);
    }
    long long base = ((long long)(rb + r0) * WOUT + s) * DD + j;
    out[base]                        = a0;
    out[base + 1LL * WOUT * DD]      = a1;
    out[base + 2LL * WOUT * DD]      = a2;
    out[base + 3LL * WOUT * DD]      = a3;
}

// ---------------- launch ----------------
extern "C" void kernel_launch(void* const* d_in, const int* in_sizes, int n_in,
                              void* d_out, int out_size)
{
    const float* x_in = (const float*)d_in[0];
    // w_out (scalar) may or may not be materialized as an input; detect via size.
    int o = (n_in > 1 && in_sizes[1] == 1) ? 2 : 1;
    const float* Wih0 = (const float*)d_in[o + 0];
    const float* Whh0 = (const float*)d_in[o + 1];
    const float* bih0 = (const float*)d_in[o + 2];
    const float* bhh0 = (const float*)d_in[o + 3];
    const float* Wih1 = (const float*)d_in[o + 4];
    const float* Whh1 = (const float*)d_in[o + 5];
    const float* bih1 = (const float*)d_in[o + 6];
    const float* bhh1 = (const float*)d_in[o + 7];
    const float* Wihd = (const float*)d_in[o + 8];
    const float* Whhd = (const float*)d_in[o + 9];
    const float* bihd = (const float*)d_in[o + 10];
    const float* bhhd = (const float*)d_in[o + 11];
    const float* Wp   = (const float*)d_in[o + 12];
    const float* bp   = (const float*)d_in[o + 13];
    const float* Wo   = (const float*)d_in[o + 14];
    const float* bo   = (const float*)d_in[o + 15];
    float* out = (float*)d_out;

    prep_kernel<<<GG, 256>>>(Wih0, Whh0, bih0, bhh0,
                             Wih1, Whh1, bih1, bhh1,
                             Wihd, Whhd, bihd, bhhd);

    // encoder: pipelined two-layer scan, 513 launches
    for (int t = 0; t <= TT; t++)
        enc_step_kernel<<<dim3(16, 8, 2), 256>>>(x_in, t);

    // decoder: 96 steps
    for (int s = 0; s < WOUT; s++) {
        const float* py = (s == 0) ? (x_in + (long long)(TT - 1) * DD)
                                   : (out + (long long)(s - 1) * DD);
        long long ldy = (s == 0) ? (long long)TT * DD : (long long)WOUT * DD;
        dec_attn_kernel<<<BB, 256>>>(py, ldy, Wp, bp, s);
        dec_lstm_kernel<<<dim3(16, 8), 256>>>(s);
        dec_y_kernel<<<16, 256>>>(out, Wo, bo, s);
    }
}